// round 6
// baseline (speedup 1.0000x reference)
#include <cuda_runtime.h>
#include <math.h>

#define N 512
#define NIMG 128
#define NFREQ 257
#define RS 65536                 // image scratch k-stride in float2 (=128*512)

#define BARSYNC(id) asm volatile("bar.sync %0, 64;" :: "r"(id) : "memory")

// ---------------- device scratch ------------------------------------------------------------
static __device__ float2 g_scratch[(size_t)NFREQ * RS];   // c-major: [k][b*512+r], ~135MB
static __device__ float2 g_hrow[(size_t)NFREQ * N];       // rowFFT of hann, [k][r], 1MB
static __device__ float2 g_tw[N];                         // W_512^k
static __device__ float  g_hann[N * N];                   // window table, 1MB
static __device__ float  g_parts[NIMG * 64];
static __device__ float  g_hparts[64];
static __device__ float  g_accum[N * NFREQ];              // half-plane sum |F|^2 (unshifted)
static __device__ float  g_psum[32][NFREQ];
static __device__ float  g_pcnt[32][NFREQ];

__device__ __forceinline__ int adr2(int i) { return i + (i >> 3); }
__device__ __forceinline__ int rev8(int i) { return ((i & 7) << 6) | (i & 56) | (i >> 6); }

// ---- packed f32x2 helpers -------------------------------------------------------------------
union F2U { float2 f; unsigned long long u; };
__device__ __forceinline__ float2 padd(float2 a, float2 b) {
    F2U A, B, C; A.f = a; B.f = b;
    asm("add.rn.f32x2 %0, %1, %2;" : "=l"(C.u) : "l"(A.u), "l"(B.u));
    return C.f;
}
__device__ __forceinline__ float2 psub(float2 a, float2 b) {
    F2U A, B, C; A.f = a; B.f = b;
    asm("fma.rn.f32x2 %0, %1, %2, %3;"
        : "=l"(C.u) : "l"(B.u), "l"(0xBF800000BF800000ULL), "l"(A.u));
    return C.f;
}
__device__ __forceinline__ float2 cmulf2(float2 a, float2 w) {
    return make_float2(a.x * w.x - a.y * w.y, a.x * w.y + a.y * w.x);
}

// ---- natural-order 8-point DFT --------------------------------------------------------------
__device__ __forceinline__ void dft8(float2* t) {
    float2 b0 = t[0], b1 = t[4], b2 = t[2], b3 = t[6];
    float2 b4 = t[1], b5 = t[5], b6 = t[3], b7 = t[7];
    float2 u0 = padd(b0, b1), u1 = psub(b0, b1), u2 = padd(b2, b3), u3 = psub(b2, b3);
    float2 u4 = padd(b4, b5), u5 = psub(b4, b5), u6 = padd(b6, b7), u7 = psub(b6, b7);
    float2 v0 = padd(u0, u2), v2 = psub(u0, u2);
    float2 v1 = make_float2(u1.x + u3.y, u1.y - u3.x);
    float2 v3 = make_float2(u1.x - u3.y, u1.y + u3.x);
    float2 v4 = padd(u4, u6), v6 = psub(u4, u6);
    float2 v5 = make_float2(u5.x + u7.y, u5.y - u7.x);
    float2 v7 = make_float2(u5.x - u7.y, u5.y + u7.x);
    const float C = 0.70710678118654752f;
    float2 a5 = make_float2(C * (v5.x + v5.y), C * (v5.y - v5.x));
    float2 a7 = make_float2(C * (v7.y - v7.x), -C * (v7.x + v7.y));
    t[0] = padd(v0, v4); t[4] = psub(v0, v4);
    t[1] = padd(v1, a5); t[5] = psub(v1, a5);
    t[2] = make_float2(v2.x + v6.y, v2.y - v6.x);
    t[6] = make_float2(v2.x - v6.y, v2.y + v6.x);
    t[3] = padd(v3, a7); t[7] = psub(v3, a7);
}

// ---------------- kernel 0: init (twiddles, hann table, zero accumulators) -------------------
__global__ void k_init() {
    int p = blockIdx.x * blockDim.x + threadIdx.x;
    {
        int i = p >> 9, j = p & 511;
        const float STEP = 512.0f / 511.0f;
        float lc = fmaf((float)j, STEP, -256.0f);
        float lr = fmaf((float)i, STEP, -256.0f);
        float rd = sqrtf(lc * lc + lr * lr);
        g_hann[p] = (rd > 256.0f) ? 0.0f : 0.5f * (1.0f + cospif(rd * (1.0f / 256.0f)));
    }
    if (p < N * NFREQ) g_accum[p] = 0.f;
    if (p < N) {
        double ang = -6.283185307179586476925286766559 * (double)p / 512.0;
        g_tw[p] = make_float2((float)cos(ang), (float)sin(ang));
    }
    if (p < 32 * NFREQ) { ((float*)g_psum)[p] = 0.f; ((float*)g_pcnt)[p] = 0.f; }
}

// ---------------- kernel 1: DIF row FFTs, 2 real rows packed per FFT -------------------------
// 4 FFTs (8 rows) per 256-thread block; per-FFT named barriers (2 warps each).
__global__ void __launch_bounds__(256) k_rowfft(const float* __restrict__ src,
                                                float2* __restrict__ dst,
                                                float* __restrict__ parts,
                                                int kstride) {
    __shared__ float2 sm[4][576];
    __shared__ float red[8];
    int b   = blockIdx.x >> 6;
    int r0  = (blockIdx.x & 63) << 3;
    int tid = threadIdx.x;
    int f   = tid >> 6, fj = tid & 63;
    int rowA = r0 + 2 * f;
    size_t srcbase = ((size_t)b << 18) + ((size_t)rowA << 9);
    const float* hA = g_hann + (rowA << 9);
    float2* s = sm[f];

    // ---- load + stage 0 (stride 64) in registers ----
    float2 t[8];
    float lsum = 0.f;
#pragma unroll
    for (int m = 0; m < 8; m++) {
        int c = fj + (m << 6);
        float va = src ? src[srcbase + c]       : 1.0f;
        float vb = src ? src[srcbase + 512 + c] : 1.0f;
        lsum += va + vb;
        t[m] = make_float2(va * hA[c], vb * hA[512 + c]);
    }
    dft8(t);
    int pb0 = fj + (fj >> 3);
#pragma unroll
    for (int q = 1; q < 8; q++) t[q] = cmulf2(t[q], g_tw[fj * q]);
#pragma unroll
    for (int q = 0; q < 8; q++) s[pb0 + 72 * q] = t[q];

    // per-warp pixel sums into smem (consumed after the block-wide pre-unpack barrier)
#pragma unroll
    for (int o = 16; o; o >>= 1) lsum += __shfl_down_sync(0xffffffffu, lsum, o);
    if ((tid & 31) == 0) red[tid >> 5] = lsum;

    BARSYNC(f + 1);

    // ---- stage 1 (stride 8) ----
    {
        int i = fj & 7, q0 = fj >> 3;
        int pb = i + 72 * q0, e = i << 3;
        float2 u[8];
#pragma unroll
        for (int m = 0; m < 8; m++) u[m] = s[pb + 9 * m];
        dft8(u);
#pragma unroll
        for (int q = 1; q < 8; q++) u[q] = cmulf2(u[q], g_tw[e * q]);
#pragma unroll
        for (int q = 0; q < 8; q++) s[pb + 9 * q] = u[q];
    }
    BARSYNC(f + 1);

    // ---- stage 2 (stride 1), no twiddle ----
    {
        int pb = 9 * fj;
        float2 u[8];
#pragma unroll
        for (int m = 0; m < 8; m++) u[m] = s[pb + m];
        dft8(u);
#pragma unroll
        for (int m = 0; m < 8; m++) s[pb + m] = u[m];
    }
    __syncthreads();               // unpack reads across FFTs; also orders red[]

    if (tid == 0) {
        float tot = 0.f;
#pragma unroll
        for (int p = 0; p < 8; p++) tot += red[p];
        parts[blockIdx.x] = tot;
    }

    // ---- Hermitian unpack + k-major (transposed) store ----
    int r = tid & 7;
    float2* so = sm[r >> 1];
    int kslot = tid >> 3;
#pragma unroll
    for (int it = 0; it < 9; it++) {
        int k = kslot + (it << 5);
        if (k < NFREQ) {
            float2 z = so[adr2(rev8(k))];
            float2 y = so[adr2(rev8((512 - k) & 511))];
            float2 o = (r & 1)
                ? make_float2(0.5f * (z.y + y.y), 0.5f * (y.x - z.x))
                : make_float2(0.5f * (z.x + y.x), 0.5f * (z.y - y.y));
            dst[(size_t)k * kstride + ((size_t)b << 9) + r0 + r] = o;
        }
    }
}

// ---------------- kernel 2: DIF column FFTs — 4 cols x 16 images, per-FFT named barriers -----
__global__ void __launch_bounds__(256, 4) k_colfft() {
    __shared__ float2 sm[4][576];
    __shared__ float smean[16];
    int ct  = blockIdx.x % 65;
    int grp = blockIdx.x / 65;               // 0..7 : 16 images each
    int cl  = threadIdx.x >> 6;
    int fj  = threadIdx.x & 63;
    int c   = (ct << 2) + cl;
    bool valid = (c < NFREQ);
    float2* s = sm[cl];
    size_t cbase = valid ? (size_t)c * RS : 0;
    int b0 = grp << 4;
    int bar = cl + 1;

    // ---- cached correction vector (invariant over image loop) ----
    float2 hv[8];
    size_t hbase = valid ? ((size_t)c << 9) : 0;
#pragma unroll
    for (int m = 0; m < 8; m++)
        hv[m] = valid ? g_hrow[hbase + fj + (m << 6)] : make_float2(0.f, 0.f);

    // ---- prefetch image 0 ----
    float2 t[8];
#pragma unroll
    for (int m = 0; m < 8; m++)
        t[m] = valid ? g_scratch[cbase + ((size_t)b0 << 9) + fj + (m << 6)]
                     : make_float2(0.f, 0.f);

    // ---- fused per-image means: warp w reduces images 2w and 2w+1 ----
    {
        int w = threadIdx.x >> 5, l = threadIdx.x & 31;
        float v1 = g_parts[((b0 + 2 * w)     << 6) + l] + g_parts[((b0 + 2 * w)     << 6) + 32 + l];
        float v2 = g_parts[((b0 + 2 * w + 1) << 6) + l] + g_parts[((b0 + 2 * w + 1) << 6) + 32 + l];
#pragma unroll
        for (int o = 16; o; o >>= 1) {
            v1 += __shfl_down_sync(0xffffffffu, v1, o);
            v2 += __shfl_down_sync(0xffffffffu, v2, o);
        }
        if (l == 0) {
            smean[2 * w]     = v1 * (1.0f / 262144.0f);
            smean[2 * w + 1] = v2 * (1.0f / 262144.0f);
        }
        __syncthreads();
    }

    int pb0 = fj + (fj >> 3);
    int i1 = fj & 7, q01 = fj >> 3;
    int pb1 = i1 + 72 * q01, e1 = i1 << 3;
    int pb2 = 9 * fj;

    float acc[8];
#pragma unroll
    for (int m = 0; m < 8; m++) acc[m] = 0.f;

    for (int bi = 0; bi < 16; bi++) {
        float mean = smean[bi];

        // stage 0 (registers): mean correction + dft8 + twiddle
        float2 tc[8];
#pragma unroll
        for (int m = 0; m < 8; m++)
            tc[m] = make_float2(fmaf(-mean, hv[m].x, t[m].x),
                                fmaf(-mean, hv[m].y, t[m].y));
        dft8(tc);
#pragma unroll
        for (int q = 1; q < 8; q++) tc[q] = cmulf2(tc[q], g_tw[fj * q]);

        BARSYNC(bar);                          // prev stage-2 reads complete (same FFT)
#pragma unroll
        for (int q = 0; q < 8; q++) s[pb0 + 72 * q] = tc[q];

        // prefetch next image into dead t — hidden across barriers + stages 1-2
        if (bi < 15 && valid) {
            int b = b0 + bi + 1;
#pragma unroll
            for (int m = 0; m < 8; m++)
                t[m] = g_scratch[cbase + ((size_t)b << 9) + fj + (m << 6)];
        }
        BARSYNC(bar);

        // stage 1
        float2 u[8];
#pragma unroll
        for (int m = 0; m < 8; m++) u[m] = s[pb1 + 9 * m];
        dft8(u);
#pragma unroll
        for (int q = 1; q < 8; q++) u[q] = cmulf2(u[q], g_tw[e1 * q]);
#pragma unroll
        for (int q = 0; q < 8; q++) s[pb1 + 9 * q] = u[q];
        BARSYNC(bar);

        // stage 2 + accumulate (no store)
#pragma unroll
        for (int m = 0; m < 8; m++) u[m] = s[pb2 + m];
        dft8(u);
#pragma unroll
        for (int m = 0; m < 8; m++)
            acc[m] = fmaf(u[m].x, u[m].x, fmaf(u[m].y, u[m].y, acc[m]));
    }

    if (valid) {
        int rlo = ((fj & 7) << 3) + (fj >> 3);
#pragma unroll
        for (int m = 0; m < 8; m++) {
            int r = (m << 6) + rlo;            // = rev8(8*fj+m)
            atomicAdd(&g_accum[r * NFREQ + c], acc[m]);
        }
    }
}

// ---------------- kernel 3: nps2D + two-level radial binning ---------------------------------
__global__ void __launch_bounds__(256) k_finalize2d(float* __restrict__ out) {
    __shared__ float ssum[NFREQ];
    __shared__ float scnt[NFREQ];
    int i = blockIdx.x;
    int tid = threadIdx.x;
    if (tid < NFREQ) { ssum[tid] = 0.f; scnt[tid] = 0.f; }
    if (tid + 256 < NFREQ) { ssum[tid + 256] = 0.f; scnt[tid + 256] = 0.f; }
    __syncthreads();

    const float SC = (float)(0.01 / (262144.0 * 128.0));
    int xi = i - 256;
#pragma unroll
    for (int h = 0; h < 2; h++) {
        int j = tid + (h << 8);
        int u = i ^ 256, v = j ^ 256;
        if (v > 256) { u = (512 - u) & 511; v = 512 - v; }
        float val = g_accum[u * NFREQ + v] * SC;
        out[NFREQ + (i << 9) + j] = val;
        int yj = j - 256;
        int rad = __double2int_rn(sqrt((double)(xi * xi + yj * yj)));
        if (rad < NFREQ) {
            atomicAdd(&ssum[rad], val);
            atomicAdd(&scnt[rad], 1.0f);
        }
    }
    __syncthreads();

    int part = i & 31;
    if (tid < NFREQ && (ssum[tid] != 0.f || scnt[tid] != 0.f)) {
        atomicAdd(&g_psum[part][tid], ssum[tid]);
        atomicAdd(&g_pcnt[part][tid], scnt[tid]);
    }
    if (tid + 256 < NFREQ && (ssum[tid + 256] != 0.f || scnt[tid + 256] != 0.f)) {
        atomicAdd(&g_psum[part][tid + 256], ssum[tid + 256]);
        atomicAdd(&g_pcnt[part][tid + 256], scnt[tid + 256]);
    }
}

// ---------------- kernel 4: nps1D and f1D ----------------------------------------------------
__global__ void k_finalize1d(float* __restrict__ out) {
    int k = threadIdx.x;
    if (k < NFREQ) {
        float s = 0.f, c = 0.f;
#pragma unroll
        for (int p = 0; p < 32; p++) { s += g_psum[p][k]; c += g_pcnt[p][k]; }
        out[k] = s / c;
        out[NFREQ + N * N + k] = 5.0f * (float)k / 256.0f;
    }
}

extern "C" void kernel_launch(void* const* d_in, const int* in_sizes, int n_in,
                              void* d_out, int out_size) {
    const float* x = (const float*)d_in[0];
    float* out = (float*)d_out;

    float* pparts;  cudaGetSymbolAddress((void**)&pparts,  g_parts);
    float* phparts; cudaGetSymbolAddress((void**)&phparts, g_hparts);
    float2* pscr;   cudaGetSymbolAddress((void**)&pscr,    g_scratch);
    float2* phrow;  cudaGetSymbolAddress((void**)&phrow,   g_hrow);

    k_init<<<1024, 256>>>();
    k_rowfft<<<NIMG * 64, 256>>>(x, pscr, pparts, RS);          // images: FFT(v*h)
    k_rowfft<<<64, 256>>>(nullptr, phrow, phparts, N);          // window: FFT(h)
    k_colfft<<<65 * 8, 256>>>();                                // 4 cols x 16 images per block
    k_finalize2d<<<N, 256>>>(out);
    k_finalize1d<<<1, NFREQ>>>(out);
}

// round 7
// speedup vs baseline: 1.0916x; 1.0916x over previous
#include <cuda_runtime.h>
#include <math.h>

#define N 512
#define NIMG 128
#define NFREQ 257
#define RS 65536                 // image scratch k-stride in float2 (=128*512)

#define BARSYNC(id) asm volatile("bar.sync %0, 64;" :: "r"(id) : "memory")

// ---------------- device scratch ------------------------------------------------------------
static __device__ float2 g_scratch[(size_t)NFREQ * RS];   // c-major: [k][b*512+r], ~135MB
static __device__ float2 g_hrow[(size_t)NFREQ * N];       // rowFFT of hann, [k][r], 1MB
static __device__ float2 g_tw[N];                         // W_512^k
static __device__ float  g_hann[N * N];                   // window table, 1MB
static __device__ float  g_parts[NIMG * 64];
static __device__ float  g_hparts[64];
static __device__ float  g_accum[N * NFREQ];              // half-plane sum |F|^2 (unshifted)
static __device__ float  g_psum[32][NFREQ];
static __device__ float  g_pcnt[32][NFREQ];

__device__ __forceinline__ int adr2(int i) { return i + (i >> 3); }

// ---- packed f32x2 helpers -------------------------------------------------------------------
union F2U { float2 f; unsigned long long u; };
__device__ __forceinline__ float2 padd(float2 a, float2 b) {
    F2U A, B, C; A.f = a; B.f = b;
    asm("add.rn.f32x2 %0, %1, %2;" : "=l"(C.u) : "l"(A.u), "l"(B.u));
    return C.f;
}
__device__ __forceinline__ float2 psub(float2 a, float2 b) {
    F2U A, B, C; A.f = a; B.f = b;
    asm("fma.rn.f32x2 %0, %1, %2, %3;"
        : "=l"(C.u) : "l"(B.u), "l"(0xBF800000BF800000ULL), "l"(A.u));
    return C.f;
}
__device__ __forceinline__ float2 cmulf2(float2 a, float2 w) {
    return make_float2(a.x * w.x - a.y * w.y, a.x * w.y + a.y * w.x);
}

// ---- natural-order 8-point DFT --------------------------------------------------------------
__device__ __forceinline__ void dft8(float2* t) {
    float2 b0 = t[0], b1 = t[4], b2 = t[2], b3 = t[6];
    float2 b4 = t[1], b5 = t[5], b6 = t[3], b7 = t[7];
    float2 u0 = padd(b0, b1), u1 = psub(b0, b1), u2 = padd(b2, b3), u3 = psub(b2, b3);
    float2 u4 = padd(b4, b5), u5 = psub(b4, b5), u6 = padd(b6, b7), u7 = psub(b6, b7);
    float2 v0 = padd(u0, u2), v2 = psub(u0, u2);
    float2 v1 = make_float2(u1.x + u3.y, u1.y - u3.x);
    float2 v3 = make_float2(u1.x - u3.y, u1.y + u3.x);
    float2 v4 = padd(u4, u6), v6 = psub(u4, u6);
    float2 v5 = make_float2(u5.x + u7.y, u5.y - u7.x);
    float2 v7 = make_float2(u5.x - u7.y, u5.y + u7.x);
    const float C = 0.70710678118654752f;
    float2 a5 = make_float2(C * (v5.x + v5.y), C * (v5.y - v5.x));
    float2 a7 = make_float2(C * (v7.y - v7.x), -C * (v7.x + v7.y));
    t[0] = padd(v0, v4); t[4] = psub(v0, v4);
    t[1] = padd(v1, a5); t[5] = psub(v1, a5);
    t[2] = make_float2(v2.x + v6.y, v2.y - v6.x);
    t[6] = make_float2(v2.x - v6.y, v2.y + v6.x);
    t[3] = padd(v3, a7); t[7] = psub(v3, a7);
}

// ---- 8x8 float2 transpose across 8 lanes (XOR network, 3 rounds) ----------------------------
// Before: lane jj holds u[q] = element jj+8q.  After: lane jj holds u[r] = element 8jj+r.
__device__ __forceinline__ void transpose8(float2* u, int jj) {
#pragma unroll
    for (int k = 0; k < 3; k++) {
        const int m = 1 << k;
        bool hi = (jj & m) != 0;
#pragma unroll
        for (int i0 = 0; i0 < 8; i0++) {
            if ((i0 & m) == 0) {
                int i1 = i0 | m;
                F2U snd; snd.f = hi ? u[i0] : u[i1];
                F2U rcv; rcv.u = __shfl_xor_sync(0xffffffffu, snd.u, m);
                if (hi) u[i0] = rcv.f; else u[i1] = rcv.f;
            }
        }
    }
}

// ---------------- kernel 0: init (twiddles, hann table, zero accumulators) -------------------
__global__ void k_init() {
    int p = blockIdx.x * blockDim.x + threadIdx.x;
    {
        int i = p >> 9, j = p & 511;
        const float STEP = 512.0f / 511.0f;
        float lc = fmaf((float)j, STEP, -256.0f);
        float lr = fmaf((float)i, STEP, -256.0f);
        float rd = sqrtf(lc * lc + lr * lr);
        g_hann[p] = (rd > 256.0f) ? 0.0f : 0.5f * (1.0f + cospif(rd * (1.0f / 256.0f)));
    }
    if (p < N * NFREQ) g_accum[p] = 0.f;
    if (p < N) {
        double ang = -6.283185307179586476925286766559 * (double)p / 512.0;
        g_tw[p] = make_float2((float)cos(ang), (float)sin(ang));
    }
    if (p < 32 * NFREQ) { ((float*)g_psum)[p] = 0.f; ((float*)g_pcnt)[p] = 0.f; }
}

// ---------------- kernel 1: DIF row FFTs, 2 real rows packed per FFT -------------------------
// 4 FFTs per 256-thread block; single SMEM exchange + shuffle transpose; 2 block barriers.
__global__ void __launch_bounds__(256) k_rowfft(const float* __restrict__ src,
                                                float2* __restrict__ dst,
                                                float* __restrict__ parts,
                                                int kstride) {
    __shared__ float2 smA[4][576];     // stage-0 output (fj-ordered)
    __shared__ float2 smB[4][576];     // final spectrum, natural frequency index
    __shared__ float red[8];
    int b   = blockIdx.x >> 6;
    int r0  = (blockIdx.x & 63) << 3;
    int tid = threadIdx.x;
    int f   = tid >> 6, tau = tid & 63;
    int g   = tau >> 3, jj = tau & 7;
    int rowA = r0 + 2 * f;
    size_t srcbase = ((size_t)b << 18) + ((size_t)rowA << 9);
    const float* hA = g_hann + (rowA << 9);
    float2* sA = smA[f];
    float2* sB = smB[f];

    // ---- load + stage 0 (stride 64) in registers ----
    float2 t[8];
    float lsum = 0.f;
#pragma unroll
    for (int m = 0; m < 8; m++) {
        int c = tau + (m << 6);
        float va = src ? src[srcbase + c]       : 1.0f;
        float vb = src ? src[srcbase + 512 + c] : 1.0f;
        lsum += va + vb;
        t[m] = make_float2(va * hA[c], vb * hA[512 + c]);
    }
    dft8(t);
    int pbS = tau + (tau >> 3);
#pragma unroll
    for (int q = 1; q < 8; q++) t[q] = cmulf2(t[q], g_tw[tau * q]);
#pragma unroll
    for (int q = 0; q < 8; q++) sA[pbS + 72 * q] = t[q];

    // per-warp pixel sums (consumed after the final block barrier)
#pragma unroll
    for (int o = 16; o; o >>= 1) lsum += __shfl_down_sync(0xffffffffu, lsum, o);
    if ((tid & 31) == 0) red[tid >> 5] = lsum;
    __syncthreads();

    // ---- stage 1 (stride 8) in registers ----
    float2 u[8];
    int pbL = 72 * g + jj;
#pragma unroll
    for (int m = 0; m < 8; m++) u[m] = sA[pbL + 9 * m];
    dft8(u);
    int e1 = jj << 3;
#pragma unroll
    for (int q = 1; q < 8; q++) u[q] = cmulf2(u[q], g_tw[e1 * q]);

    // ---- exchange via shuffle + stage 2 in registers ----
    transpose8(u, jj);
    dft8(u);

    // store at natural frequency index: element pos 64g+8jj+m holds X[64m+8jj+g]
#pragma unroll
    for (int m = 0; m < 8; m++)
        sB[adr2((m << 6) + (jj << 3) + g)] = u[m];
    __syncthreads();

    if (tid == 0) {
        float tot = 0.f;
#pragma unroll
        for (int p = 0; p < 8; p++) tot += red[p];
        parts[blockIdx.x] = tot;
    }

    // ---- Hermitian unpack + k-major (transposed) store ----
    int r = tid & 7;
    float2* so = smB[r >> 1];
    int kslot = tid >> 3;
#pragma unroll
    for (int it = 0; it < 9; it++) {
        int k = kslot + (it << 5);
        if (k < NFREQ) {
            float2 z = so[adr2(k)];
            float2 y = so[adr2((512 - k) & 511)];
            float2 o = (r & 1)
                ? make_float2(0.5f * (z.y + y.y), 0.5f * (y.x - z.x))
                : make_float2(0.5f * (z.x + y.x), 0.5f * (z.y - y.y));
            dst[(size_t)k * kstride + ((size_t)b << 9) + r0 + r] = o;
        }
    }
}

// ---------------- kernel 2: DIF column FFTs — 4 cols x 8 images, 1 barrier/image -------------
__global__ void __launch_bounds__(256, 4) k_colfft() {
    __shared__ float2 smbuf[2][4][576];    // double-buffered stage-0 output
    __shared__ float smean[8];
    int ct  = blockIdx.x % 65;
    int grp = blockIdx.x / 65;             // 0..15 : 8 images each
    int f   = threadIdx.x >> 6;
    int tau = threadIdx.x & 63;
    int g   = tau >> 3, jj = tau & 7;
    int c   = (ct << 2) + f;
    bool valid = (c < NFREQ);
    size_t cbase = valid ? (size_t)c * RS : 0;
    int b0 = grp << 3;
    int bar = f + 1;

    // ---- cached correction vector (invariant over image loop) ----
    float2 hv[8];
    size_t hbase = valid ? ((size_t)c << 9) : 0;
#pragma unroll
    for (int m = 0; m < 8; m++)
        hv[m] = valid ? g_hrow[hbase + tau + (m << 6)] : make_float2(0.f, 0.f);

    // ---- prefetch image 0 ----
    float2 t[8];
#pragma unroll
    for (int m = 0; m < 8; m++)
        t[m] = valid ? g_scratch[cbase + ((size_t)b0 << 9) + tau + (m << 6)]
                     : make_float2(0.f, 0.f);

    // ---- fused per-image means: warp w reduces image b0+w ----
    {
        int w = threadIdx.x >> 5, l = threadIdx.x & 31;
        float v = g_parts[((b0 + w) << 6) + l] + g_parts[((b0 + w) << 6) + 32 + l];
#pragma unroll
        for (int o = 16; o; o >>= 1) v += __shfl_down_sync(0xffffffffu, v, o);
        if (l == 0) smean[w] = v * (1.0f / 262144.0f);
        __syncthreads();
    }

    int pbS = tau + (tau >> 3);
    int pbL = 72 * g + jj;
    int e1 = jj << 3;

    float acc[8];
#pragma unroll
    for (int m = 0; m < 8; m++) acc[m] = 0.f;

    for (int bi = 0; bi < 8; bi++) {
        float mean = smean[bi];
        float2* s = smbuf[bi & 1][f];

        // stage 0 (registers): mean correction + dft8 + twiddle
        float2 tc[8];
#pragma unroll
        for (int m = 0; m < 8; m++)
            tc[m] = make_float2(fmaf(-mean, hv[m].x, t[m].x),
                                fmaf(-mean, hv[m].y, t[m].y));
        dft8(tc);
#pragma unroll
        for (int q = 1; q < 8; q++) tc[q] = cmulf2(tc[q], g_tw[tau * q]);
#pragma unroll
        for (int q = 0; q < 8; q++) s[pbS + 72 * q] = tc[q];

        // prefetch next image into dead t — hidden across barrier + stages 1-2
        if (bi < 7 && valid) {
            int b = b0 + bi + 1;
#pragma unroll
            for (int m = 0; m < 8; m++)
                t[m] = g_scratch[cbase + ((size_t)b << 9) + tau + (m << 6)];
        }
        BARSYNC(bar);     // data-ready; WAR vs image bi-2 guaranteed by double buffer

        // stage 1 in registers
        float2 u[8];
#pragma unroll
        for (int m = 0; m < 8; m++) u[m] = s[pbL + 9 * m];
        dft8(u);
#pragma unroll
        for (int q = 1; q < 8; q++) u[q] = cmulf2(u[q], g_tw[e1 * q]);

        // shuffle exchange + stage 2 + accumulate
        transpose8(u, jj);
        dft8(u);
#pragma unroll
        for (int m = 0; m < 8; m++)
            acc[m] = fmaf(u[m].x, u[m].x, fmaf(u[m].y, u[m].y, acc[m]));
    }

    if (valid) {
        int rlo = (jj << 3) + g;
#pragma unroll
        for (int m = 0; m < 8; m++) {
            int r = (m << 6) + rlo;            // natural frequency index
            atomicAdd(&g_accum[r * NFREQ + c], acc[m]);
        }
    }
}

// ---------------- kernel 3: nps2D + two-level radial binning ---------------------------------
__global__ void __launch_bounds__(256) k_finalize2d(float* __restrict__ out) {
    __shared__ float ssum[NFREQ];
    __shared__ float scnt[NFREQ];
    int i = blockIdx.x;
    int tid = threadIdx.x;
    if (tid < NFREQ) { ssum[tid] = 0.f; scnt[tid] = 0.f; }
    if (tid + 256 < NFREQ) { ssum[tid + 256] = 0.f; scnt[tid + 256] = 0.f; }
    __syncthreads();

    const float SC = (float)(0.01 / (262144.0 * 128.0));
    int xi = i - 256;
#pragma unroll
    for (int h = 0; h < 2; h++) {
        int j = tid + (h << 8);
        int u = i ^ 256, v = j ^ 256;
        if (v > 256) { u = (512 - u) & 511; v = 512 - v; }
        float val = g_accum[u * NFREQ + v] * SC;
        out[NFREQ + (i << 9) + j] = val;
        int yj = j - 256;
        // exact: |sqrtf err| ~3e-5 << 1e-3 min distance of sqrt(int) to a .5 boundary
        int rad = __float2int_rn(__fsqrt_rn((float)(xi * xi + yj * yj)));
        if (rad < NFREQ) {
            atomicAdd(&ssum[rad], val);
            atomicAdd(&scnt[rad], 1.0f);
        }
    }
    __syncthreads();

    int part = i & 31;
    if (tid < NFREQ && (ssum[tid] != 0.f || scnt[tid] != 0.f)) {
        atomicAdd(&g_psum[part][tid], ssum[tid]);
        atomicAdd(&g_pcnt[part][tid], scnt[tid]);
    }
    if (tid + 256 < NFREQ && (ssum[tid + 256] != 0.f || scnt[tid + 256] != 0.f)) {
        atomicAdd(&g_psum[part][tid + 256], ssum[tid + 256]);
        atomicAdd(&g_pcnt[part][tid + 256], scnt[tid + 256]);
    }
}

// ---------------- kernel 4: nps1D and f1D ----------------------------------------------------
__global__ void k_finalize1d(float* __restrict__ out) {
    int k = threadIdx.x;
    if (k < NFREQ) {
        float s = 0.f, c = 0.f;
#pragma unroll
        for (int p = 0; p < 32; p++) { s += g_psum[p][k]; c += g_pcnt[p][k]; }
        out[k] = s / c;
        out[NFREQ + N * N + k] = 5.0f * (float)k / 256.0f;
    }
}

extern "C" void kernel_launch(void* const* d_in, const int* in_sizes, int n_in,
                              void* d_out, int out_size) {
    const float* x = (const float*)d_in[0];
    float* out = (float*)d_out;

    float* pparts;  cudaGetSymbolAddress((void**)&pparts,  g_parts);
    float* phparts; cudaGetSymbolAddress((void**)&phparts, g_hparts);
    float2* pscr;   cudaGetSymbolAddress((void**)&pscr,    g_scratch);
    float2* phrow;  cudaGetSymbolAddress((void**)&phrow,   g_hrow);

    k_init<<<1024, 256>>>();
    k_rowfft<<<NIMG * 64, 256>>>(x, pscr, pparts, RS);          // images: FFT(v*h)
    k_rowfft<<<64, 256>>>(nullptr, phrow, phparts, N);          // window: FFT(h)
    k_colfft<<<65 * 16, 256>>>();                               // 4 cols x 8 images per block
    k_finalize2d<<<N, 256>>>(out);
    k_finalize1d<<<1, NFREQ>>>(out);
}

// round 8
// speedup vs baseline: 1.1896x; 1.0897x over previous
#include <cuda_runtime.h>
#include <cuda_fp16.h>
#include <math.h>

#define N 512
#define NIMG 128
#define NFREQ 257
#define RS 65536                 // image scratch k-stride in half2 (=128*512)

#define BARSYNC(id) asm volatile("bar.sync %0, 64;" :: "r"(id) : "memory")

// ---------------- device scratch ------------------------------------------------------------
static __device__ __half2 g_scratch[(size_t)NFREQ * RS];  // c-major: [k][b*512+r], ~67MB, fp16
static __device__ __half2 g_hrow[(size_t)NFREQ * N];      // rowFFT of hann, [k][r], 0.5MB
static __device__ float2  g_tw[N];                        // W_512^k
static __device__ float   g_hann[N * N];                  // window table, 1MB
static __device__ float   g_parts[NIMG * 64];
static __device__ float   g_hparts[64];
static __device__ float   g_accum[N * NFREQ];             // half-plane sum |F|^2 (unshifted)
static __device__ float   g_psum[32][NFREQ];
static __device__ float   g_pcnt[32][NFREQ];

__device__ __forceinline__ int adr2(int i) { return i + (i >> 3); }

// ---- packed f32x2 helpers -------------------------------------------------------------------
union F2U { float2 f; unsigned long long u; };
__device__ __forceinline__ float2 padd(float2 a, float2 b) {
    F2U A, B, C; A.f = a; B.f = b;
    asm("add.rn.f32x2 %0, %1, %2;" : "=l"(C.u) : "l"(A.u), "l"(B.u));
    return C.f;
}
__device__ __forceinline__ float2 psub(float2 a, float2 b) {
    F2U A, B, C; A.f = a; B.f = b;
    asm("fma.rn.f32x2 %0, %1, %2, %3;"
        : "=l"(C.u) : "l"(B.u), "l"(0xBF800000BF800000ULL), "l"(A.u));
    return C.f;
}
__device__ __forceinline__ float2 cmulf2(float2 a, float2 w) {
    return make_float2(a.x * w.x - a.y * w.y, a.x * w.y + a.y * w.x);
}

// ---- natural-order 8-point DFT --------------------------------------------------------------
__device__ __forceinline__ void dft8(float2* t) {
    float2 b0 = t[0], b1 = t[4], b2 = t[2], b3 = t[6];
    float2 b4 = t[1], b5 = t[5], b6 = t[3], b7 = t[7];
    float2 u0 = padd(b0, b1), u1 = psub(b0, b1), u2 = padd(b2, b3), u3 = psub(b2, b3);
    float2 u4 = padd(b4, b5), u5 = psub(b4, b5), u6 = padd(b6, b7), u7 = psub(b6, b7);
    float2 v0 = padd(u0, u2), v2 = psub(u0, u2);
    float2 v1 = make_float2(u1.x + u3.y, u1.y - u3.x);
    float2 v3 = make_float2(u1.x - u3.y, u1.y + u3.x);
    float2 v4 = padd(u4, u6), v6 = psub(u4, u6);
    float2 v5 = make_float2(u5.x + u7.y, u5.y - u7.x);
    float2 v7 = make_float2(u5.x - u7.y, u5.y + u7.x);
    const float C = 0.70710678118654752f;
    float2 a5 = make_float2(C * (v5.x + v5.y), C * (v5.y - v5.x));
    float2 a7 = make_float2(C * (v7.y - v7.x), -C * (v7.x + v7.y));
    t[0] = padd(v0, v4); t[4] = psub(v0, v4);
    t[1] = padd(v1, a5); t[5] = psub(v1, a5);
    t[2] = make_float2(v2.x + v6.y, v2.y - v6.x);
    t[6] = make_float2(v2.x - v6.y, v2.y + v6.x);
    t[3] = padd(v3, a7); t[7] = psub(v3, a7);
}

// ---- 8x8 float2 transpose across 8 lanes (XOR network, 3 rounds) ----------------------------
__device__ __forceinline__ void transpose8(float2* u, int jj) {
#pragma unroll
    for (int k = 0; k < 3; k++) {
        const int m = 1 << k;
        bool hi = (jj & m) != 0;
#pragma unroll
        for (int i0 = 0; i0 < 8; i0++) {
            if ((i0 & m) == 0) {
                int i1 = i0 | m;
                F2U snd; snd.f = hi ? u[i0] : u[i1];
                F2U rcv; rcv.u = __shfl_xor_sync(0xffffffffu, snd.u, m);
                if (hi) u[i0] = rcv.f; else u[i1] = rcv.f;
            }
        }
    }
}

// ---------------- kernel 0: init (twiddles, hann table, zero accumulators) -------------------
__global__ void k_init() {
    int p = blockIdx.x * blockDim.x + threadIdx.x;
    {
        int i = p >> 9, j = p & 511;
        const float STEP = 512.0f / 511.0f;
        float lc = fmaf((float)j, STEP, -256.0f);
        float lr = fmaf((float)i, STEP, -256.0f);
        float rd = sqrtf(lc * lc + lr * lr);
        g_hann[p] = (rd > 256.0f) ? 0.0f : 0.5f * (1.0f + cospif(rd * (1.0f / 256.0f)));
    }
    if (p < N * NFREQ) g_accum[p] = 0.f;
    if (p < N) {
        double ang = -6.283185307179586476925286766559 * (double)p / 512.0;
        g_tw[p] = make_float2((float)cos(ang), (float)sin(ang));
    }
    if (p < 32 * NFREQ) { ((float*)g_psum)[p] = 0.f; ((float*)g_pcnt)[p] = 0.f; }
}

// ---------------- kernel 1: DIF row FFTs, 2 real rows packed per FFT -------------------------
// 4 FFTs per 256-thread block; single SMEM exchange + shuffle transpose; fp16 output.
__global__ void __launch_bounds__(256) k_rowfft(const float* __restrict__ src,
                                                __half2* __restrict__ dst,
                                                float* __restrict__ parts,
                                                int kstride) {
    __shared__ float2 smA[4][576];     // stage-0 output
    __shared__ float2 smB[4][576];     // final spectrum, natural frequency index
    __shared__ float red[8];
    int b   = blockIdx.x >> 6;
    int r0  = (blockIdx.x & 63) << 3;
    int tid = threadIdx.x;
    int f   = tid >> 6, tau = tid & 63;
    int g   = tau >> 3, jj = tau & 7;
    int rowA = r0 + 2 * f;
    size_t srcbase = ((size_t)b << 18) + ((size_t)rowA << 9);
    const float* hA = g_hann + (rowA << 9);
    float2* sA = smA[f];
    float2* sB = smB[f];

    // ---- load + stage 0 (stride 64) in registers ----
    float2 t[8];
    float lsum = 0.f;
#pragma unroll
    for (int m = 0; m < 8; m++) {
        int c = tau + (m << 6);
        float va = src ? src[srcbase + c]       : 1.0f;
        float vb = src ? src[srcbase + 512 + c] : 1.0f;
        lsum += va + vb;
        t[m] = make_float2(va * hA[c], vb * hA[512 + c]);
    }
    dft8(t);
    int pbS = tau + (tau >> 3);
#pragma unroll
    for (int q = 1; q < 8; q++) t[q] = cmulf2(t[q], g_tw[tau * q]);
#pragma unroll
    for (int q = 0; q < 8; q++) sA[pbS + 72 * q] = t[q];

    // per-warp pixel sums (consumed after the final block barrier)
#pragma unroll
    for (int o = 16; o; o >>= 1) lsum += __shfl_down_sync(0xffffffffu, lsum, o);
    if ((tid & 31) == 0) red[tid >> 5] = lsum;
    __syncthreads();

    // ---- stage 1 (stride 8) in registers ----
    float2 u[8];
    int pbL = 72 * g + jj;
#pragma unroll
    for (int m = 0; m < 8; m++) u[m] = sA[pbL + 9 * m];
    dft8(u);
    int e1 = jj << 3;
#pragma unroll
    for (int q = 1; q < 8; q++) u[q] = cmulf2(u[q], g_tw[e1 * q]);

    // ---- exchange via shuffle + stage 2 in registers ----
    transpose8(u, jj);
    dft8(u);

    // store at natural frequency index
#pragma unroll
    for (int m = 0; m < 8; m++)
        sB[adr2((m << 6) + (jj << 3) + g)] = u[m];
    __syncthreads();

    if (tid == 0) {
        float tot = 0.f;
#pragma unroll
        for (int p = 0; p < 8; p++) tot += red[p];
        parts[blockIdx.x] = tot;
    }

    // ---- Hermitian unpack + k-major (transposed) fp16 store ----
    int r = tid & 7;
    float2* so = smB[r >> 1];
    int kslot = tid >> 3;
#pragma unroll
    for (int it = 0; it < 9; it++) {
        int k = kslot + (it << 5);
        if (k < NFREQ) {
            float2 z = so[adr2(k)];
            float2 y = so[adr2((512 - k) & 511)];
            float2 o = (r & 1)
                ? make_float2(0.5f * (z.y + y.y), 0.5f * (y.x - z.x))
                : make_float2(0.5f * (z.x + y.x), 0.5f * (z.y - y.y));
            dst[(size_t)k * kstride + ((size_t)b << 9) + r0 + r] =
                __floats2half2_rn(o.x, o.y);
        }
    }
}

// ---------------- kernel 2: DIF column FFTs — 4 cols x 8 images, 1 barrier/image -------------
__global__ void __launch_bounds__(256, 4) k_colfft() {
    __shared__ float2 smbuf[2][4][576];    // double-buffered stage-0 output
    __shared__ float smean[8];
    int ct  = blockIdx.x % 65;
    int grp = blockIdx.x / 65;             // 0..15 : 8 images each
    int f   = threadIdx.x >> 6;
    int tau = threadIdx.x & 63;
    int g   = tau >> 3, jj = tau & 7;
    int c   = (ct << 2) + f;
    bool valid = (c < NFREQ);
    size_t cbase = valid ? (size_t)c * RS : 0;
    int b0 = grp << 3;
    int bar = f + 1;

    // ---- cached correction vector (invariant over image loop), fp32 in regs ----
    float2 hv[8];
    size_t hbase = valid ? ((size_t)c << 9) : 0;
#pragma unroll
    for (int m = 0; m < 8; m++)
        hv[m] = valid ? __half22float2(g_hrow[hbase + tau + (m << 6)])
                      : make_float2(0.f, 0.f);

    // ---- prefetch image 0 (raw fp16, converted at use) ----
    __half2 traw[8];
#pragma unroll
    for (int m = 0; m < 8; m++)
        traw[m] = valid ? g_scratch[cbase + ((size_t)b0 << 9) + tau + (m << 6)]
                        : __half2(__float2half2_rn(0.f));

    // ---- fused per-image means: warp w reduces image b0+w ----
    {
        int w = threadIdx.x >> 5, l = threadIdx.x & 31;
        float v = g_parts[((b0 + w) << 6) + l] + g_parts[((b0 + w) << 6) + 32 + l];
#pragma unroll
        for (int o = 16; o; o >>= 1) v += __shfl_down_sync(0xffffffffu, v, o);
        if (l == 0) smean[w] = v * (1.0f / 262144.0f);
        __syncthreads();
    }

    int pbS = tau + (tau >> 3);
    int pbL = 72 * g + jj;
    int e1 = jj << 3;

    float acc[8];
#pragma unroll
    for (int m = 0; m < 8; m++) acc[m] = 0.f;

    for (int bi = 0; bi < 8; bi++) {
        float mean = smean[bi];
        float2* s = smbuf[bi & 1][f];

        // stage 0 (registers): convert + mean correction + dft8 + twiddle
        float2 tc[8];
#pragma unroll
        for (int m = 0; m < 8; m++) {
            float2 v = __half22float2(traw[m]);
            tc[m] = make_float2(fmaf(-mean, hv[m].x, v.x),
                                fmaf(-mean, hv[m].y, v.y));
        }
        dft8(tc);
#pragma unroll
        for (int q = 1; q < 8; q++) tc[q] = cmulf2(tc[q], g_tw[tau * q]);
#pragma unroll
        for (int q = 0; q < 8; q++) s[pbS + 72 * q] = tc[q];

        // prefetch next image into dead traw — hidden across barrier + stages 1-2
        if (bi < 7 && valid) {
            int b = b0 + bi + 1;
#pragma unroll
            for (int m = 0; m < 8; m++)
                traw[m] = g_scratch[cbase + ((size_t)b << 9) + tau + (m << 6)];
        }
        BARSYNC(bar);     // data-ready; WAR vs image bi-2 guaranteed by double buffer

        // stage 1 in registers
        float2 u[8];
#pragma unroll
        for (int m = 0; m < 8; m++) u[m] = s[pbL + 9 * m];
        dft8(u);
#pragma unroll
        for (int q = 1; q < 8; q++) u[q] = cmulf2(u[q], g_tw[e1 * q]);

        // shuffle exchange + stage 2 + accumulate
        transpose8(u, jj);
        dft8(u);
#pragma unroll
        for (int m = 0; m < 8; m++)
            acc[m] = fmaf(u[m].x, u[m].x, fmaf(u[m].y, u[m].y, acc[m]));
    }

    if (valid) {
        int rlo = (jj << 3) + g;
#pragma unroll
        for (int m = 0; m < 8; m++) {
            int r = (m << 6) + rlo;            // natural frequency index
            atomicAdd(&g_accum[r * NFREQ + c], acc[m]);
        }
    }
}

// ---------------- kernel 3: nps2D + two-level radial binning ---------------------------------
__global__ void __launch_bounds__(256) k_finalize2d(float* __restrict__ out) {
    __shared__ float ssum[NFREQ];
    __shared__ float scnt[NFREQ];
    int i = blockIdx.x;
    int tid = threadIdx.x;
    if (tid < NFREQ) { ssum[tid] = 0.f; scnt[tid] = 0.f; }
    if (tid + 256 < NFREQ) { ssum[tid + 256] = 0.f; scnt[tid + 256] = 0.f; }
    __syncthreads();

    const float SC = (float)(0.01 / (262144.0 * 128.0));
    int xi = i - 256;
#pragma unroll
    for (int h = 0; h < 2; h++) {
        int j = tid + (h << 8);
        int u = i ^ 256, v = j ^ 256;
        if (v > 256) { u = (512 - u) & 511; v = 512 - v; }
        float val = g_accum[u * NFREQ + v] * SC;
        out[NFREQ + (i << 9) + j] = val;
        int yj = j - 256;
        int rad = __float2int_rn(__fsqrt_rn((float)(xi * xi + yj * yj)));
        if (rad < NFREQ) {
            atomicAdd(&ssum[rad], val);
            atomicAdd(&scnt[rad], 1.0f);
        }
    }
    __syncthreads();

    int part = i & 31;
    if (tid < NFREQ && (ssum[tid] != 0.f || scnt[tid] != 0.f)) {
        atomicAdd(&g_psum[part][tid], ssum[tid]);
        atomicAdd(&g_pcnt[part][tid], scnt[tid]);
    }
    if (tid + 256 < NFREQ && (ssum[tid + 256] != 0.f || scnt[tid + 256] != 0.f)) {
        atomicAdd(&g_psum[part][tid + 256], ssum[tid + 256]);
        atomicAdd(&g_pcnt[part][tid + 256], scnt[tid + 256]);
    }
}

// ---------------- kernel 4: nps1D and f1D ----------------------------------------------------
__global__ void k_finalize1d(float* __restrict__ out) {
    int k = threadIdx.x;
    if (k < NFREQ) {
        float s = 0.f, c = 0.f;
#pragma unroll
        for (int p = 0; p < 32; p++) { s += g_psum[p][k]; c += g_pcnt[p][k]; }
        out[k] = s / c;
        out[NFREQ + N * N + k] = 5.0f * (float)k / 256.0f;
    }
}

extern "C" void kernel_launch(void* const* d_in, const int* in_sizes, int n_in,
                              void* d_out, int out_size) {
    const float* x = (const float*)d_in[0];
    float* out = (float*)d_out;

    float* pparts;   cudaGetSymbolAddress((void**)&pparts,   g_parts);
    float* phparts;  cudaGetSymbolAddress((void**)&phparts,  g_hparts);
    __half2* pscr;   cudaGetSymbolAddress((void**)&pscr,     g_scratch);
    __half2* phrow;  cudaGetSymbolAddress((void**)&phrow,    g_hrow);

    k_init<<<1024, 256>>>();
    k_rowfft<<<NIMG * 64, 256>>>(x, pscr, pparts, RS);          // images: FFT(v*h)
    k_rowfft<<<64, 256>>>(nullptr, phrow, phparts, N);          // window: FFT(h)
    k_colfft<<<65 * 16, 256>>>();                               // 4 cols x 8 images per block
    k_finalize2d<<<N, 256>>>(out);
    k_finalize1d<<<1, NFREQ>>>(out);
}